// round 7
// baseline (speedup 1.0000x reference)
#include <cuda_runtime.h>
#include <math.h>

#define N_NODES 100000
#define N_EDGES 1600000
#define D_FEAT  64
#define EPS     1e-7f
#define FULL    0xffffffffu

// Scratch
__device__ float g_inv[N_NODES];          // 1 / ||x_i||
__device__ int   g_col[N_EDGES];          // edge_col as int32
__device__ int   g_rowptr[N_NODES + 1];

// ---------------------------------------------------------------------------
// Dtype detection: edge values random in [0, N_NODES); int64 -> high words 0.
// ---------------------------------------------------------------------------
__device__ __forceinline__ int detect_is64(const unsigned int* ec_raw)
{
    unsigned acc = 0;
    #pragma unroll
    for (int i = 1; i < 16; i += 2) acc |= ec_raw[i];
    return acc == 0u;
}

__device__ __forceinline__ int get_idx(const void* p, int e, int is64)
{
    if (is64) return (int)((const long long*)p)[e];
    return ((const int*)p)[e];
}

// ---------------------------------------------------------------------------
// Prep kernel: three jobs via block-range split.
// ---------------------------------------------------------------------------
#define B_NORM 6250     // N_NODES*16 / 256
#define B_COL  6250     // N_EDGES / 256
#define B_ROW  391      // ceil((N_NODES+1)/256)

__global__ void __launch_bounds__(256)
prep_kernel(const float4* __restrict__ x4,
            const void* __restrict__ er,
            const void* __restrict__ ec)
{
    int b = blockIdx.x;
    if (b < B_NORM) {
        int t    = b * 256 + threadIdx.x;
        int node = t >> 4;
        int sub  = t & 15;
        if (node >= N_NODES) return;
        float4 a = x4[node * 16 + sub];
        float s = a.x * a.x + a.y * a.y + a.z * a.z + a.w * a.w;
        #pragma unroll
        for (int o = 8; o; o >>= 1) s += __shfl_xor_sync(FULL, s, o);
        if (sub == 0) g_inv[node] = rsqrtf(s);
    } else if (b < B_NORM + B_COL) {
        int e = (b - B_NORM) * 256 + threadIdx.x;
        if (e >= N_EDGES) return;
        int is64 = detect_is64((const unsigned int*)ec);
        g_col[e] = get_idx(ec, e, is64);
    } else {
        int i = (b - B_NORM - B_COL) * 256 + threadIdx.x;
        if (i > N_NODES) return;
        int is64 = detect_is64((const unsigned int*)ec);
        int lo = 0, hi = N_EDGES;
        while (lo < hi) {
            int mid = (lo + hi) >> 1;
            if (get_idx(er, mid, is64) < i) lo = mid + 1; else hi = mid;
        }
        g_rowptr[i] = lo;
    }
}

// ---------------------------------------------------------------------------
// Fused sim + softmax + SPMM. ONE WARP PER ROW.
// Lane = (edge group g in 0..1) x (feature f in 0..15): 2 edges in flight,
// each edge's 64-float row = 16 lanes x float4 (perfectly coalesced 256B).
// Softmax as w = exp(beta*(cos-1)): shift-invariant, arg<=0, no running max.
// Low register footprint (one float4 each for xr/b/acc) -> high occupancy;
// unroll 4 gives 4 independent gather chains per warp.
// ---------------------------------------------------------------------------
__global__ void __launch_bounds__(256, 5)
fused_row_kernel(const float4* __restrict__ x4,
                 const float* __restrict__ beta,
                 float4* __restrict__ out4)
{
    int warp = (blockIdx.x * blockDim.x + threadIdx.x) >> 5;
    if (warp >= N_NODES) return;
    int lane = threadIdx.x & 31;
    int g = lane >> 4;                    // edge slot (0..1)
    int f = lane & 15;                    // feature slice (float4 index)

    int row = warp;
    int s = g_rowptr[row];
    int n = g_rowptr[row + 1] - s;

    float4 xr = x4[row * 16 + f];
    float  bv = beta[0];
    float  bs = bv * g_inv[row];          // beta / ||x_r||

    float4 acc  = make_float4(0.f, 0.f, 0.f, 0.f);
    float  wsum = 0.f;

    const int* __restrict__ col = g_col;

    for (int base = 0; base < n; base += 32) {
        int rem = n - base;               // edges in this chunk (clamped below)
        int cnt = rem < 32 ? rem : 32;

        // cooperative prefetch of up to 32 indices + inverse norms
        int   myc   = (lane < cnt) ? col[s + base + lane] : row;
        float myinv = g_inv[myc];

        int iters = (cnt + 1) >> 1;       // 2 edges per iteration
        #pragma unroll 4
        for (int it = 0; it < iters; ++it) {
            int   src   = it * 2 + g;
            int   c     = __shfl_sync(FULL, myc, src);
            float invnc = __shfl_sync(FULL, myinv, src);
            bool  valid = src < cnt;

            float4 b = x4[c * 16 + f];

            float d = b.x * xr.x + b.y * xr.y + b.z * xr.z + b.w * xr.w;
            d += __shfl_xor_sync(FULL, d, 1);
            d += __shfl_xor_sync(FULL, d, 2);
            d += __shfl_xor_sync(FULL, d, 4);
            d += __shfl_xor_sync(FULL, d, 8);

            float w = __expf(fmaf(bs * invnc, d, -bv));  // exp(beta*(cos-1))
            w = valid ? w : 0.f;

            wsum += w;
            acc.x = fmaf(w, b.x, acc.x);
            acc.y = fmaf(w, b.y, acc.y);
            acc.z = fmaf(w, b.z, acc.z);
            acc.w = fmaf(w, b.w, acc.w);
        }
    }

    // combine the two edge-groups (single butterfly step)
    acc.x += __shfl_xor_sync(FULL, acc.x, 16);
    acc.y += __shfl_xor_sync(FULL, acc.y, 16);
    acc.z += __shfl_xor_sync(FULL, acc.z, 16);
    acc.w += __shfl_xor_sync(FULL, acc.w, 16);
    wsum  += __shfl_xor_sync(FULL, wsum,  16);

    if (g == 0) {
        float inv = (n > 0) ? (1.f / wsum) : 0.f;
        out4[row * 16 + f] = make_float4(acc.x * inv, acc.y * inv,
                                         acc.z * inv, acc.w * inv);
    }
}

// ---------------------------------------------------------------------------
extern "C" void kernel_launch(void* const* d_in, const int* in_sizes, int n_in,
                              void* d_out, int out_size)
{
    const float4* x    = 0;
    const float*  beta = 0;
    const void*   er   = 0;
    const void*   ec   = 0;
    for (int i = 0; i < n_in; ++i) {
        long long sz = in_sizes[i];
        if (sz == (long long)N_NODES * D_FEAT) x = (const float4*)d_in[i];
        else if (sz == 1)                      beta = (const float*)d_in[i];
        else if (sz == N_EDGES) {
            if (!er) er = d_in[i]; else ec = d_in[i];
        }
    }
    float4* out = (float4*)d_out;

    prep_kernel<<<B_NORM + B_COL + B_ROW, 256>>>(x, er, ec);

    {   // one warp per row
        long long total = (long long)N_NODES * 32;
        int blocks = (int)((total + 255) / 256);
        fused_row_kernel<<<blocks, 256>>>(x, beta, out);
    }
}